// round 16
// baseline (speedup 1.0000x reference)
#include <cuda_runtime.h>
#include <math.h>

#define NN 50000
#define NE 1250000
#define F  64
#define ED 7
#define CSR_BLOCKS 98
#define CSR_THREADS 512
#define NG ((NN + 7) / 8)      // 6250 node groups (8 nodes/warp)
#define NB_G ((NG + 7) / 8)    // 782 blocks of 8 warps

// ---------------- scratch (static device memory; no allocs) ----------------
__device__ float g_feats[3][NN * F];
__device__ float g_n1[NN * F];
__device__ float g_r[NN];
__device__ float g_t[NN * F];
__device__ int   g_rowptr[NN + 1];
__device__ int   g_cursor[NN];
__device__ int   g_counts[NN];         // zeroed at load; re-zeroed inside k_csr
__device__ int   g_bsums[CSR_BLOCKS];
__device__ int    g_src[NE + 8];       // +pad: prefetch may read 2 past end (pads stay 0 = valid node)
__device__ float4 g_ea8[2 * NE + 16];
__device__ unsigned g_bar;             // monotonic ticket barrier (never reset)

__device__ __forceinline__ float lrelu(float x) { return fmaxf(x, 0.01f * x); }

__device__ __forceinline__ void grid_barrier() {
    __syncthreads();
    if (threadIdx.x == 0) {
        __threadfence();
        unsigned ticket = atomicAdd(&g_bar, 1u);
        unsigned target = (ticket / CSR_BLOCKS + 1u) * CSR_BLOCKS;
        while (*(volatile unsigned*)&g_bar < target) { }
        __threadfence();
    }
    __syncthreads();
}

// ---------------- fused CSR build (98 blocks, measured-best) ----------------
__global__ void k_csr(const int* __restrict__ ei, const float* __restrict__ eattr) {
    __shared__ int sh[CSR_THREADS];
    __shared__ int s_base;
    int t = threadIdx.x, b = blockIdx.x;
    const int STRIDE = CSR_BLOCKS * CSR_THREADS;

    for (int e = b * CSR_THREADS + t; e < NE; e += STRIDE)
        atomicAdd(&g_counts[ei[NE + e]], 1);
    grid_barrier();

    int i = b * CSR_THREADS + t;
    int v = (i < NN) ? g_counts[i] : 0;
    if (i < NN) g_counts[i] = 0;
    sh[t] = v;
    __syncthreads();
#pragma unroll
    for (int o = 1; o < CSR_THREADS; o <<= 1) {
        int u = (t >= o) ? sh[t - o] : 0;
        __syncthreads();
        sh[t] += u;
        __syncthreads();
    }
    int local_excl = sh[t] - v;
    if (t == CSR_THREADS - 1) g_bsums[b] = sh[t];
    grid_barrier();
    if (t == 0) {
        int base = 0;
        for (int j = 0; j < b; j++) base += g_bsums[j];
        s_base = base;
    }
    __syncthreads();
    if (i < NN) {
        int r = local_excl + s_base;
        g_rowptr[i] = r;
        g_cursor[i] = r;
    }
    if (b == 0 && t == 0) g_rowptr[NN] = NE;
    grid_barrier();

    for (int e = b * CSR_THREADS + t; e < NE; e += STRIDE) {
        int d = ei[NE + e];
        int pos = atomicAdd(&g_cursor[d], 1);
        g_src[pos] = ei[e];
        const float* ea = eattr + (long long)e * ED;
        g_ea8[2 * pos]     = make_float4(ea[0], ea[1], ea[2], ea[3]);
        g_ea8[2 * pos + 1] = make_float4(ea[4], ea[5], ea[6], 0.f);
    }
}

// ---------------- gather + prep layer0: blocked, 8 nodes/warp (unchanged) ----------------
__global__ void k_gprep(const int* __restrict__ x, const float* __restrict__ emb,
                        const float* __restrict__ w1, const float* __restrict__ ar) {
    __shared__ float s_w[F * F];
    __shared__ float s_ar[F];
    __shared__ float s_x[8][8 * F];
    int tid = threadIdx.x;
    for (int i = tid; i < F * F; i += 256) s_w[i] = w1[i];
    if (tid < F) s_ar[tid] = ar[tid];
    __syncthreads();
    int warp = tid >> 5, lane = tid & 31;
    int gi = blockIdx.x * 8 + warp;
    if (gi >= NG) return;
    int n0 = gi * 8;
    float2 ar2 = reinterpret_cast<const float2*>(s_ar)[lane];
    float* sx = &s_x[warp][0];

    float pr[8];
#pragma unroll
    for (int n = 0; n < 8; n++) {
        int node = n0 + n;
        float2 h2 = make_float2(0.f, 0.f);
        if (node < NN) {
            long long row = (long long)x[node] * F;
            h2 = reinterpret_cast<const float2*>(emb + row)[lane];
            reinterpret_cast<float2*>(g_feats[0] + node * F)[lane] = h2;
        }
        reinterpret_cast<float2*>(sx + n * F)[lane] = h2;
        pr[n] = h2.x * ar2.x + h2.y * ar2.y;
    }
    __syncwarp();

    float2 acc[8];
#pragma unroll
    for (int n = 0; n < 8; n++) acc[n] = make_float2(0.f, 0.f);
#pragma unroll 16
    for (int k = 0; k < F; k++) {
        float2 w = reinterpret_cast<const float2*>(s_w + k * F)[lane];
#pragma unroll
        for (int n = 0; n < 8; n++) {
            float hv = sx[n * F + k];
            acc[n].x = fmaf(hv, w.x, acc[n].x);
            acc[n].y = fmaf(hv, w.y, acc[n].y);
        }
    }
#pragma unroll
    for (int o = 16; o; o >>= 1)
#pragma unroll
        for (int n = 0; n < 8; n++) pr[n] += __shfl_xor_sync(0xffffffffu, pr[n], o);
#pragma unroll
    for (int n = 0; n < 8; n++) {
        int node = n0 + n;
        if (node < NN) {
            reinterpret_cast<float2*>(g_n1 + node * F)[lane] = acc[n];
            if (lane == 0) g_r[node] = pr[n];
        }
    }
}

// ---------------- edge kernel: warp/node, 2-edge ILP + v-prefetch (src->v chain off critical path) ----------------
__global__ void k_edge(const float* __restrict__ w1, const float* __restrict__ al) {
    int tid = threadIdx.x;
    int warp = tid >> 5, lane = tid & 31;
    int node = blockIdx.x * 8 + warp;
    if (node >= NN) return;

    const float* wb = w1 + F * F;
    float2 w0 = reinterpret_cast<const float2*>(wb + 0 * F)[lane];
    float2 w1v = reinterpret_cast<const float2*>(wb + 1 * F)[lane];
    float2 w2v = reinterpret_cast<const float2*>(wb + 2 * F)[lane];
    float2 w3v = reinterpret_cast<const float2*>(wb + 3 * F)[lane];
    float2 w4v = reinterpret_cast<const float2*>(wb + 4 * F)[lane];
    float2 w5v = reinterpret_cast<const float2*>(wb + 5 * F)[lane];
    float2 w6v = reinterpret_cast<const float2*>(wb + 6 * F)[lane];
    float2 al2 = reinterpret_cast<const float2*>(al)[lane];
    float ri = g_r[node];

    int beg = g_rowptr[node], end = g_rowptr[node + 1];
    float sA = 0.f, aA0 = 0.f, aA1 = 0.f;
    float sB = 0.f, aB0 = 0.f, aB1 = 0.f;

    const float2* n1v2 = reinterpret_cast<const float2*>(g_n1);

    // ---- pipeline prime: v for pair 0 (one-time dependent chain; pads are node 0 = valid) ----
    int sAc = g_src[beg], sBc = g_src[beg + 1];
    float2 vA = __ldg(&n1v2[sAc * (F / 2) + lane]);
    float2 vB = __ldg(&n1v2[sBc * (F / 2) + lane]);

    int p = beg;
    for (; p + 2 <= end; p += 2) {
        // prefetch NEXT pair: src (sequential, L1 hit) -> n1 rows (L2 random);
        // consumed only next iteration, so the L2 latency hides behind this body
        int sAn = g_src[p + 2], sBn = g_src[p + 3];
        float2 vAn = __ldg(&n1v2[sAn * (F / 2) + lane]);
        float2 vBn = __ldg(&n1v2[sBn * (F / 2) + lane]);
        // current pair edge_attr (sequential, mostly L1 hits)
        float4 eA0 = g_ea8[2 * p],     eA1 = g_ea8[2 * p + 1];
        float4 eB0 = g_ea8[2 * p + 2], eB1 = g_ea8[2 * p + 3];

        float cA0 = eA0.x * w0.x + eA0.y * w1v.x + eA0.z * w2v.x + eA0.w * w3v.x
                  + eA1.x * w4v.x + eA1.y * w5v.x + eA1.z * w6v.x;
        float cA1 = eA0.x * w0.y + eA0.y * w1v.y + eA0.z * w2v.y + eA0.w * w3v.y
                  + eA1.x * w4v.y + eA1.y * w5v.y + eA1.z * w6v.y;
        float cB0 = eB0.x * w0.x + eB0.y * w1v.x + eB0.z * w2v.x + eB0.w * w3v.x
                  + eB1.x * w4v.x + eB1.y * w5v.x + eB1.z * w6v.x;
        float cB1 = eB0.x * w0.y + eB0.y * w1v.y + eB0.z * w2v.y + eB0.w * w3v.y
                  + eB1.x * w4v.y + eB1.y * w5v.y + eB1.z * w6v.y;

        float xA0 = lrelu(vA.x + cA0), xA1 = lrelu(vA.y + cA1);
        float xB0 = lrelu(vB.x + cB0), xB1 = lrelu(vB.y + cB1);
        float pA = xA0 * al2.x + xA1 * al2.y;
        float pB = xB0 * al2.x + xB1 * al2.y;
#pragma unroll
        for (int o = 16; o; o >>= 1) {
            pA += __shfl_xor_sync(0xffffffffu, pA, o);
            pB += __shfl_xor_sync(0xffffffffu, pB, o);
        }
        float wA = __expf(lrelu(pA + ri));
        float wB = __expf(lrelu(pB + ri));
        sA += wA;  aA0 = fmaf(wA, xA0, aA0);  aA1 = fmaf(wA, xA1, aA1);
        sB += wB;  aB0 = fmaf(wB, xB0, aB0);  aB1 = fmaf(wB, xB1, aB1);
        vA = vAn; vB = vBn;
    }
    if (p < end) {  // remainder (exactly 1 edge) — its v is already in vA
        float4 e0 = g_ea8[2 * p], e1 = g_ea8[2 * p + 1];
        float c0 = e0.x * w0.x + e0.y * w1v.x + e0.z * w2v.x + e0.w * w3v.x
                 + e1.x * w4v.x + e1.y * w5v.x + e1.z * w6v.x;
        float c1 = e0.x * w0.y + e0.y * w1v.y + e0.z * w2v.y + e0.w * w3v.y
                 + e1.x * w4v.y + e1.y * w5v.y + e1.z * w6v.y;
        float x0 = lrelu(vA.x + c0), x1 = lrelu(vA.y + c1);
        float pp = x0 * al2.x + x1 * al2.y;
#pragma unroll
        for (int o = 16; o; o >>= 1) pp += __shfl_xor_sync(0xffffffffu, pp, o);
        float w = __expf(lrelu(pp + ri));
        sA += w;  aA0 = fmaf(w, x0, aA0);  aA1 = fmaf(w, x1, aA1);
    }
    float inv = 1.f / (sA + sB + 1e-16f);
    reinterpret_cast<float2*>(g_t + node * F)[lane] =
        make_float2((aA0 + aB0) * inv, (aA1 + aB1) * inv);
}

// ---------------- update layer l + prep layer l+1: blocked (unchanged) ----------------
__global__ void k_upprep(const float* __restrict__ w2, const float* __restrict__ b,
                         const float* __restrict__ w1n, const float* __restrict__ arn,
                         int lout) {
    __shared__ float s_w2[F * F];
    __shared__ float s_w1[F * F];
    __shared__ float s_b[F];
    __shared__ float s_ar[F];
    __shared__ float s_x[8][8 * F];
    int tid = threadIdx.x;
    for (int i = tid; i < F * F; i += 256) { s_w2[i] = w2[i]; s_w1[i] = w1n[i]; }
    if (tid < F) { s_b[tid] = b[tid]; s_ar[tid] = arn[tid]; }
    __syncthreads();
    int warp = tid >> 5, lane = tid & 31;
    int gi = blockIdx.x * 8 + warp;
    if (gi >= NG) return;
    int n0 = gi * 8;
    float2 bb  = reinterpret_cast<const float2*>(s_b)[lane];
    float2 ar2 = reinterpret_cast<const float2*>(s_ar)[lane];
    float* sx = &s_x[warp][0];

#pragma unroll
    for (int n = 0; n < 8; n++) {
        int node = n0 + n;
        float2 v = (node < NN) ? reinterpret_cast<const float2*>(g_t + node * F)[lane]
                               : make_float2(0.f, 0.f);
        reinterpret_cast<float2*>(sx + n * F)[lane] = v;
    }
    __syncwarp();

    float2 acc[8];
#pragma unroll
    for (int n = 0; n < 8; n++) acc[n] = bb;
#pragma unroll 16
    for (int k = 0; k < F; k++) {
        float2 w = reinterpret_cast<const float2*>(s_w2 + k * F)[lane];
#pragma unroll
        for (int n = 0; n < 8; n++) {
            float hv = sx[n * F + k];
            acc[n].x = fmaf(hv, w.x, acc[n].x);
            acc[n].y = fmaf(hv, w.y, acc[n].y);
        }
    }
    __syncwarp();

    float pr[8];
#pragma unroll
    for (int n = 0; n < 8; n++) {
        float2 h2 = make_float2(fmaxf(acc[n].x, 0.f), fmaxf(acc[n].y, 0.f));
        int node = n0 + n;
        if (node < NN)
            reinterpret_cast<float2*>(g_feats[lout] + node * F)[lane] = h2;
        reinterpret_cast<float2*>(sx + n * F)[lane] = h2;
        pr[n] = h2.x * ar2.x + h2.y * ar2.y;
        acc[n] = make_float2(0.f, 0.f);
    }
    __syncwarp();

#pragma unroll 16
    for (int k = 0; k < F; k++) {
        float2 w = reinterpret_cast<const float2*>(s_w1 + k * F)[lane];
#pragma unroll
        for (int n = 0; n < 8; n++) {
            float hv = sx[n * F + k];
            acc[n].x = fmaf(hv, w.x, acc[n].x);
            acc[n].y = fmaf(hv, w.y, acc[n].y);
        }
    }
#pragma unroll
    for (int o = 16; o; o >>= 1)
#pragma unroll
        for (int n = 0; n < 8; n++) pr[n] += __shfl_xor_sync(0xffffffffu, pr[n], o);
#pragma unroll
    for (int n = 0; n < 8; n++) {
        int node = n0 + n;
        if (node < NN) {
            reinterpret_cast<float2*>(g_n1 + node * F)[lane] = acc[n];
            if (lane == 0) g_r[node] = pr[n];
        }
    }
}

// ---------------- update layer2 + head: blocked GEMM + chunked blocked head (unchanged) ----------------
__global__ void k_uphead(const float* __restrict__ w2, const float* __restrict__ b,
                         const float* __restrict__ fc1, const float* __restrict__ b1,
                         const float* __restrict__ fc2, const float* __restrict__ b2,
                         float* __restrict__ out) {
    __shared__ float s_w2[F * F];
    __shared__ float s_fc1[256 * 20];
    __shared__ float s_fc2[20];
    __shared__ float s_b1[20];
    __shared__ float s_b[F];
    __shared__ float s_x[8][8 * F];
    int tid = threadIdx.x;
    for (int i = tid; i < F * F; i += 256) s_w2[i] = w2[i];
    for (int i = tid; i < 256 * 20; i += 256) s_fc1[i] = fc1[i];
    if (tid < F) s_b[tid] = b[tid];
    if (tid < 20) { s_fc2[tid] = fc2[tid]; s_b1[tid] = b1[tid]; }
    __syncthreads();
    int warp = tid >> 5, lane = tid & 31;
    int gi = blockIdx.x * 8 + warp;
    if (gi >= NG) return;
    int n0 = gi * 8;
    float2 bb = reinterpret_cast<const float2*>(s_b)[lane];
    float b2v = b2[0];
    float* sx = &s_x[warp][0];

#pragma unroll
    for (int n = 0; n < 8; n++) {
        int node = n0 + n;
        float2 v = (node < NN) ? reinterpret_cast<const float2*>(g_t + node * F)[lane]
                               : make_float2(0.f, 0.f);
        reinterpret_cast<float2*>(sx + n * F)[lane] = v;
    }
    __syncwarp();
    float2 acc[8];
#pragma unroll
    for (int n = 0; n < 8; n++) acc[n] = bb;
#pragma unroll 16
    for (int k = 0; k < F; k++) {
        float2 w = reinterpret_cast<const float2*>(s_w2 + k * F)[lane];
#pragma unroll
        for (int n = 0; n < 8; n++) {
            float hv = sx[n * F + k];
            acc[n].x = fmaf(hv, w.x, acc[n].x);
            acc[n].y = fmaf(hv, w.y, acc[n].y);
        }
    }

    float z[8];
#pragma unroll
    for (int n = 0; n < 8; n++) z[n] = 0.f;
#pragma unroll
    for (int c = 0; c < 4; c++) {
        __syncwarp();
        if (c < 3) {
#pragma unroll
            for (int n = 0; n < 8; n++) {
                int node = n0 + n;
                float2 v = (node < NN)
                    ? reinterpret_cast<const float2*>(g_feats[c] + node * F)[lane]
                    : make_float2(0.f, 0.f);
                reinterpret_cast<float2*>(sx + n * F)[lane] = v;
            }
        } else {
#pragma unroll
            for (int n = 0; n < 8; n++)
                reinterpret_cast<float2*>(sx + n * F)[lane] =
                    make_float2(fmaxf(acc[n].x, 0.f), fmaxf(acc[n].y, 0.f));
        }
        __syncwarp();
        if (lane < 20) {
#pragma unroll 8
            for (int k = 0; k < 64; k++) {
                float w = s_fc1[(c * 64 + k) * 20 + lane];
#pragma unroll
                for (int n = 0; n < 8; n++)
                    z[n] = fmaf(sx[n * F + k], w, z[n]);
            }
        }
    }
#pragma unroll
    for (int n = 0; n < 8; n++) {
        float zv = (lane < 20) ? fmaxf(z[n] + s_b1[lane], 0.f) * s_fc2[lane] : 0.f;
#pragma unroll
        for (int o = 16; o; o >>= 1) zv += __shfl_xor_sync(0xffffffffu, zv, o);
        int node = n0 + n;
        if (lane == 0 && node < NN)
            out[node] = 1.f / (1.f + __expf(-(zv + b2v)));
    }
}

// ---------------- launch ----------------
extern "C" void kernel_launch(void* const* d_in, const int* in_sizes, int n_in,
                              void* d_out, int out_size) {
    const int*   x     = (const int*)  d_in[0];
    const int*   ei    = (const int*)  d_in[1];   // [2, E]
    const float* eattr = (const float*)d_in[2];   // [E, 7]
    const float* emb   = (const float*)d_in[3];   // [VOCAB, 64]
    const float* lin1  = (const float*)d_in[4];   // [3, 71, 64]
    const float* attl  = (const float*)d_in[5];   // [3, 64]
    const float* attr_ = (const float*)d_in[6];   // [3, 64]
    const float* lin2  = (const float*)d_in[7];   // [3, 64, 64]
    const float* gb    = (const float*)d_in[8];   // [3, 64]
    const float* fc1   = (const float*)d_in[9];   // [256, 20]
    const float* fb1   = (const float*)d_in[10];  // [20]
    const float* fc2   = (const float*)d_in[11];  // [20, 1]
    const float* fb2   = (const float*)d_in[12];  // [1]
    float* out = (float*)d_out;

    int nb = (NN + 7) / 8;  // edge kernel: warp per node

    k_csr<<<CSR_BLOCKS, CSR_THREADS>>>(ei, eattr);                   // 0
    k_gprep<<<NB_G, 256>>>(x, emb, lin1, attr_);                     // 1
    k_edge<<<nb, 256>>>(lin1, attl);                                 // 2
    k_upprep<<<NB_G, 256>>>(lin2, gb, lin1 + 1 * 71 * F, attr_ + 1 * F, 1);  // 3 <- PROFILED (clock canary)
    k_edge<<<nb, 256>>>(lin1 + 1 * 71 * F, attl + 1 * F);
    k_upprep<<<NB_G, 256>>>(lin2 + 1 * F * F, gb + 1 * F, lin1 + 2 * 71 * F, attr_ + 2 * F, 2);
    k_edge<<<nb, 256>>>(lin1 + 2 * 71 * F, attl + 2 * F);
    k_uphead<<<NB_G, 256>>>(lin2 + 2 * F * F, gb + 2 * F, fc1, fb1, fc2, fb2, out);
}

// round 17
// speedup vs baseline: 1.0260x; 1.0260x over previous
#include <cuda_runtime.h>
#include <math.h>

#define NN 50000
#define NE 1250000
#define F  64
#define ED 7
#define CSR_BLOCKS 98
#define CSR_THREADS 512
#define NG ((NN + 7) / 8)      // 6250 node groups (8 nodes/warp)
#define NB_G ((NG + 7) / 8)    // 782 blocks of 8 warps

// ---------------- scratch (static device memory; no allocs) ----------------
__device__ float g_feats[3][NN * F];
__device__ float g_n1[NN * F];
__device__ float g_r[NN];
__device__ float g_t[NN * F];
__device__ int   g_rowptr[NN + 1];
__device__ int   g_cursor[NN];
__device__ int   g_counts[NN];         // zeroed at load; re-zeroed inside k_csr
__device__ int   g_bsums[CSR_BLOCKS];
__device__ int    g_src[NE + 8];
__device__ float4 g_ea8[2 * NE + 16];
__device__ unsigned g_bar;             // monotonic ticket barrier (never reset)

__device__ __forceinline__ float lrelu(float x) { return fmaxf(x, 0.01f * x); }

__device__ __forceinline__ void grid_barrier() {
    __syncthreads();
    if (threadIdx.x == 0) {
        __threadfence();
        unsigned ticket = atomicAdd(&g_bar, 1u);
        unsigned target = (ticket / CSR_BLOCKS + 1u) * CSR_BLOCKS;
        while (*(volatile unsigned*)&g_bar < target) { }
        __threadfence();
    }
    __syncthreads();
}

// ---------------- fused CSR build (98 blocks, measured-best) ----------------
__global__ void k_csr(const int* __restrict__ ei, const float* __restrict__ eattr) {
    __shared__ int sh[CSR_THREADS];
    __shared__ int s_base;
    int t = threadIdx.x, b = blockIdx.x;
    const int STRIDE = CSR_BLOCKS * CSR_THREADS;

    for (int e = b * CSR_THREADS + t; e < NE; e += STRIDE)
        atomicAdd(&g_counts[ei[NE + e]], 1);
    grid_barrier();

    int i = b * CSR_THREADS + t;
    int v = (i < NN) ? g_counts[i] : 0;
    if (i < NN) g_counts[i] = 0;
    sh[t] = v;
    __syncthreads();
#pragma unroll
    for (int o = 1; o < CSR_THREADS; o <<= 1) {
        int u = (t >= o) ? sh[t - o] : 0;
        __syncthreads();
        sh[t] += u;
        __syncthreads();
    }
    int local_excl = sh[t] - v;
    if (t == CSR_THREADS - 1) g_bsums[b] = sh[t];
    grid_barrier();
    if (t == 0) {
        int base = 0;
        for (int j = 0; j < b; j++) base += g_bsums[j];
        s_base = base;
    }
    __syncthreads();
    if (i < NN) {
        int r = local_excl + s_base;
        g_rowptr[i] = r;
        g_cursor[i] = r;
    }
    if (b == 0 && t == 0) g_rowptr[NN] = NE;
    grid_barrier();

    for (int e = b * CSR_THREADS + t; e < NE; e += STRIDE) {
        int d = ei[NE + e];
        int pos = atomicAdd(&g_cursor[d], 1);
        g_src[pos] = ei[e];
        const float* ea = eattr + (long long)e * ED;
        g_ea8[2 * pos]     = make_float4(ea[0], ea[1], ea[2], ea[3]);
        g_ea8[2 * pos + 1] = make_float4(ea[4], ea[5], ea[6], 0.f);
    }
}

// ---------------- gather + prep layer0: blocked, 8 nodes/warp (unchanged) ----------------
__global__ void k_gprep(const int* __restrict__ x, const float* __restrict__ emb,
                        const float* __restrict__ w1, const float* __restrict__ ar) {
    __shared__ float s_w[F * F];
    __shared__ float s_ar[F];
    __shared__ float s_x[8][8 * F];
    int tid = threadIdx.x;
    for (int i = tid; i < F * F; i += 256) s_w[i] = w1[i];
    if (tid < F) s_ar[tid] = ar[tid];
    __syncthreads();
    int warp = tid >> 5, lane = tid & 31;
    int gi = blockIdx.x * 8 + warp;
    if (gi >= NG) return;
    int n0 = gi * 8;
    float2 ar2 = reinterpret_cast<const float2*>(s_ar)[lane];
    float* sx = &s_x[warp][0];

    float pr[8];
#pragma unroll
    for (int n = 0; n < 8; n++) {
        int node = n0 + n;
        float2 h2 = make_float2(0.f, 0.f);
        if (node < NN) {
            long long row = (long long)x[node] * F;
            h2 = reinterpret_cast<const float2*>(emb + row)[lane];
            reinterpret_cast<float2*>(g_feats[0] + node * F)[lane] = h2;
        }
        reinterpret_cast<float2*>(sx + n * F)[lane] = h2;
        pr[n] = h2.x * ar2.x + h2.y * ar2.y;
    }
    __syncwarp();

    float2 acc[8];
#pragma unroll
    for (int n = 0; n < 8; n++) acc[n] = make_float2(0.f, 0.f);
#pragma unroll 16
    for (int k = 0; k < F; k++) {
        float2 w = reinterpret_cast<const float2*>(s_w + k * F)[lane];
#pragma unroll
        for (int n = 0; n < 8; n++) {
            float hv = sx[n * F + k];
            acc[n].x = fmaf(hv, w.x, acc[n].x);
            acc[n].y = fmaf(hv, w.y, acc[n].y);
        }
    }
#pragma unroll
    for (int o = 16; o; o >>= 1)
#pragma unroll
        for (int n = 0; n < 8; n++) pr[n] += __shfl_xor_sync(0xffffffffu, pr[n], o);
#pragma unroll
    for (int n = 0; n < 8; n++) {
        int node = n0 + n;
        if (node < NN) {
            reinterpret_cast<float2*>(g_n1 + node * F)[lane] = acc[n];
            if (lane == 0) g_r[node] = pr[n];
        }
    }
}

// ---------------- edge kernel: warp/node, 2-edge ILP, 6-shuffle dual reduction ----------------
__global__ void k_edge(const float* __restrict__ w1, const float* __restrict__ al) {
    int tid = threadIdx.x;
    int warp = tid >> 5, lane = tid & 31;
    int node = blockIdx.x * 8 + warp;
    if (node >= NN) return;
    bool lo = (lane < 16);

    const float* wb = w1 + F * F;
    float2 w0 = reinterpret_cast<const float2*>(wb + 0 * F)[lane];
    float2 w1v = reinterpret_cast<const float2*>(wb + 1 * F)[lane];
    float2 w2v = reinterpret_cast<const float2*>(wb + 2 * F)[lane];
    float2 w3v = reinterpret_cast<const float2*>(wb + 3 * F)[lane];
    float2 w4v = reinterpret_cast<const float2*>(wb + 4 * F)[lane];
    float2 w5v = reinterpret_cast<const float2*>(wb + 5 * F)[lane];
    float2 w6v = reinterpret_cast<const float2*>(wb + 6 * F)[lane];
    float2 al2 = reinterpret_cast<const float2*>(al)[lane];
    float ri = g_r[node];

    int beg = g_rowptr[node], end = g_rowptr[node + 1];
    float sA = 0.f, aA0 = 0.f, aA1 = 0.f;
    float sB = 0.f, aB0 = 0.f, aB1 = 0.f;

    int p = beg;
    for (; p + 2 <= end; p += 2) {
        int srcA = g_src[p], srcB = g_src[p + 1];
        float4 eA0 = g_ea8[2 * p],     eA1 = g_ea8[2 * p + 1];
        float4 eB0 = g_ea8[2 * p + 2], eB1 = g_ea8[2 * p + 3];
        float2 vA = reinterpret_cast<const float2*>(g_n1 + srcA * F)[lane];
        float2 vB = reinterpret_cast<const float2*>(g_n1 + srcB * F)[lane];

        float cA0 = eA0.x * w0.x + eA0.y * w1v.x + eA0.z * w2v.x + eA0.w * w3v.x
                  + eA1.x * w4v.x + eA1.y * w5v.x + eA1.z * w6v.x;
        float cA1 = eA0.x * w0.y + eA0.y * w1v.y + eA0.z * w2v.y + eA0.w * w3v.y
                  + eA1.x * w4v.y + eA1.y * w5v.y + eA1.z * w6v.y;
        float cB0 = eB0.x * w0.x + eB0.y * w1v.x + eB0.z * w2v.x + eB0.w * w3v.x
                  + eB1.x * w4v.x + eB1.y * w5v.x + eB1.z * w6v.x;
        float cB1 = eB0.x * w0.y + eB0.y * w1v.y + eB0.z * w2v.y + eB0.w * w3v.y
                  + eB1.x * w4v.y + eB1.y * w5v.y + eB1.z * w6v.y;

        float xA0 = lrelu(vA.x + cA0), xA1 = lrelu(vA.y + cA1);
        float xB0 = lrelu(vB.x + cB0), xB1 = lrelu(vB.y + cB1);
        float pA = xA0 * al2.x + xA1 * al2.y;
        float pB = xB0 * al2.x + xB1 * al2.y;

        // dual reduction: 6 shuffles compute both 32-lane sums
        float c = lo ? pA : pB;
        float d = lo ? pB : pA;
        c += __shfl_xor_sync(0xffffffffu, d, 16);   // half-sums: lo lanes pair pA, hi lanes pair pB
#pragma unroll
        for (int o = 8; o; o >>= 1) c += __shfl_xor_sync(0xffffffffu, c, o);
        float other = __shfl_xor_sync(0xffffffffu, c, 16);
        float sumA = lo ? c : other;
        float sumB = lo ? other : c;

        float wA = __expf(lrelu(sumA + ri));
        float wB = __expf(lrelu(sumB + ri));
        sA += wA;  aA0 = fmaf(wA, xA0, aA0);  aA1 = fmaf(wA, xA1, aA1);
        sB += wB;  aB0 = fmaf(wB, xB0, aB0);  aB1 = fmaf(wB, xB1, aB1);
    }
    if (p < end) {
        int src = g_src[p];
        float4 e0 = g_ea8[2 * p], e1 = g_ea8[2 * p + 1];
        float2 v = reinterpret_cast<const float2*>(g_n1 + src * F)[lane];
        float c0 = e0.x * w0.x + e0.y * w1v.x + e0.z * w2v.x + e0.w * w3v.x
                 + e1.x * w4v.x + e1.y * w5v.x + e1.z * w6v.x;
        float c1 = e0.x * w0.y + e0.y * w1v.y + e0.z * w2v.y + e0.w * w3v.y
                 + e1.x * w4v.y + e1.y * w5v.y + e1.z * w6v.y;
        float x0 = lrelu(v.x + c0), x1 = lrelu(v.y + c1);
        float pp = x0 * al2.x + x1 * al2.y;
#pragma unroll
        for (int o = 16; o; o >>= 1) pp += __shfl_xor_sync(0xffffffffu, pp, o);
        float w = __expf(lrelu(pp + ri));
        sA += w;  aA0 = fmaf(w, x0, aA0);  aA1 = fmaf(w, x1, aA1);
    }
    float inv = 1.f / (sA + sB + 1e-16f);
    reinterpret_cast<float2*>(g_t + node * F)[lane] =
        make_float2((aA0 + aB0) * inv, (aA1 + aB1) * inv);
}

// ---------------- update layer l + prep layer l+1: blocked (unchanged) ----------------
__global__ void k_upprep(const float* __restrict__ w2, const float* __restrict__ b,
                         const float* __restrict__ w1n, const float* __restrict__ arn,
                         int lout) {
    __shared__ float s_w2[F * F];
    __shared__ float s_w1[F * F];
    __shared__ float s_b[F];
    __shared__ float s_ar[F];
    __shared__ float s_x[8][8 * F];
    int tid = threadIdx.x;
    for (int i = tid; i < F * F; i += 256) { s_w2[i] = w2[i]; s_w1[i] = w1n[i]; }
    if (tid < F) { s_b[tid] = b[tid]; s_ar[tid] = arn[tid]; }
    __syncthreads();
    int warp = tid >> 5, lane = tid & 31;
    int gi = blockIdx.x * 8 + warp;
    if (gi >= NG) return;
    int n0 = gi * 8;
    float2 bb  = reinterpret_cast<const float2*>(s_b)[lane];
    float2 ar2 = reinterpret_cast<const float2*>(s_ar)[lane];
    float* sx = &s_x[warp][0];

#pragma unroll
    for (int n = 0; n < 8; n++) {
        int node = n0 + n;
        float2 v = (node < NN) ? reinterpret_cast<const float2*>(g_t + node * F)[lane]
                               : make_float2(0.f, 0.f);
        reinterpret_cast<float2*>(sx + n * F)[lane] = v;
    }
    __syncwarp();

    float2 acc[8];
#pragma unroll
    for (int n = 0; n < 8; n++) acc[n] = bb;
#pragma unroll 16
    for (int k = 0; k < F; k++) {
        float2 w = reinterpret_cast<const float2*>(s_w2 + k * F)[lane];
#pragma unroll
        for (int n = 0; n < 8; n++) {
            float hv = sx[n * F + k];
            acc[n].x = fmaf(hv, w.x, acc[n].x);
            acc[n].y = fmaf(hv, w.y, acc[n].y);
        }
    }
    __syncwarp();

    float pr[8];
#pragma unroll
    for (int n = 0; n < 8; n++) {
        float2 h2 = make_float2(fmaxf(acc[n].x, 0.f), fmaxf(acc[n].y, 0.f));
        int node = n0 + n;
        if (node < NN)
            reinterpret_cast<float2*>(g_feats[lout] + node * F)[lane] = h2;
        reinterpret_cast<float2*>(sx + n * F)[lane] = h2;
        pr[n] = h2.x * ar2.x + h2.y * ar2.y;
        acc[n] = make_float2(0.f, 0.f);
    }
    __syncwarp();

#pragma unroll 16
    for (int k = 0; k < F; k++) {
        float2 w = reinterpret_cast<const float2*>(s_w1 + k * F)[lane];
#pragma unroll
        for (int n = 0; n < 8; n++) {
            float hv = sx[n * F + k];
            acc[n].x = fmaf(hv, w.x, acc[n].x);
            acc[n].y = fmaf(hv, w.y, acc[n].y);
        }
    }
#pragma unroll
    for (int o = 16; o; o >>= 1)
#pragma unroll
        for (int n = 0; n < 8; n++) pr[n] += __shfl_xor_sync(0xffffffffu, pr[n], o);
#pragma unroll
    for (int n = 0; n < 8; n++) {
        int node = n0 + n;
        if (node < NN) {
            reinterpret_cast<float2*>(g_n1 + node * F)[lane] = acc[n];
            if (lane == 0) g_r[node] = pr[n];
        }
    }
}

// ---------------- update layer2 + head: blocked GEMM + chunked blocked head (unchanged) ----------------
__global__ void k_uphead(const float* __restrict__ w2, const float* __restrict__ b,
                         const float* __restrict__ fc1, const float* __restrict__ b1,
                         const float* __restrict__ fc2, const float* __restrict__ b2,
                         float* __restrict__ out) {
    __shared__ float s_w2[F * F];
    __shared__ float s_fc1[256 * 20];
    __shared__ float s_fc2[20];
    __shared__ float s_b1[20];
    __shared__ float s_b[F];
    __shared__ float s_x[8][8 * F];
    int tid = threadIdx.x;
    for (int i = tid; i < F * F; i += 256) s_w2[i] = w2[i];
    for (int i = tid; i < 256 * 20; i += 256) s_fc1[i] = fc1[i];
    if (tid < F) s_b[tid] = b[tid];
    if (tid < 20) { s_fc2[tid] = fc2[tid]; s_b1[tid] = b1[tid]; }
    __syncthreads();
    int warp = tid >> 5, lane = tid & 31;
    int gi = blockIdx.x * 8 + warp;
    if (gi >= NG) return;
    int n0 = gi * 8;
    float2 bb = reinterpret_cast<const float2*>(s_b)[lane];
    float b2v = b2[0];
    float* sx = &s_x[warp][0];

#pragma unroll
    for (int n = 0; n < 8; n++) {
        int node = n0 + n;
        float2 v = (node < NN) ? reinterpret_cast<const float2*>(g_t + node * F)[lane]
                               : make_float2(0.f, 0.f);
        reinterpret_cast<float2*>(sx + n * F)[lane] = v;
    }
    __syncwarp();
    float2 acc[8];
#pragma unroll
    for (int n = 0; n < 8; n++) acc[n] = bb;
#pragma unroll 16
    for (int k = 0; k < F; k++) {
        float2 w = reinterpret_cast<const float2*>(s_w2 + k * F)[lane];
#pragma unroll
        for (int n = 0; n < 8; n++) {
            float hv = sx[n * F + k];
            acc[n].x = fmaf(hv, w.x, acc[n].x);
            acc[n].y = fmaf(hv, w.y, acc[n].y);
        }
    }

    float z[8];
#pragma unroll
    for (int n = 0; n < 8; n++) z[n] = 0.f;
#pragma unroll
    for (int c = 0; c < 4; c++) {
        __syncwarp();
        if (c < 3) {
#pragma unroll
            for (int n = 0; n < 8; n++) {
                int node = n0 + n;
                float2 v = (node < NN)
                    ? reinterpret_cast<const float2*>(g_feats[c] + node * F)[lane]
                    : make_float2(0.f, 0.f);
                reinterpret_cast<float2*>(sx + n * F)[lane] = v;
            }
        } else {
#pragma unroll
            for (int n = 0; n < 8; n++)
                reinterpret_cast<float2*>(sx + n * F)[lane] =
                    make_float2(fmaxf(acc[n].x, 0.f), fmaxf(acc[n].y, 0.f));
        }
        __syncwarp();
        if (lane < 20) {
#pragma unroll 8
            for (int k = 0; k < 64; k++) {
                float w = s_fc1[(c * 64 + k) * 20 + lane];
#pragma unroll
                for (int n = 0; n < 8; n++)
                    z[n] = fmaf(sx[n * F + k], w, z[n]);
            }
        }
    }
#pragma unroll
    for (int n = 0; n < 8; n++) {
        float zv = (lane < 20) ? fmaxf(z[n] + s_b1[lane], 0.f) * s_fc2[lane] : 0.f;
#pragma unroll
        for (int o = 16; o; o >>= 1) zv += __shfl_xor_sync(0xffffffffu, zv, o);
        int node = n0 + n;
        if (lane == 0 && node < NN)
            out[node] = 1.f / (1.f + __expf(-(zv + b2v)));
    }
}

// ---------------- launch ----------------
extern "C" void kernel_launch(void* const* d_in, const int* in_sizes, int n_in,
                              void* d_out, int out_size) {
    const int*   x     = (const int*)  d_in[0];
    const int*   ei    = (const int*)  d_in[1];   // [2, E]
    const float* eattr = (const float*)d_in[2];   // [E, 7]
    const float* emb   = (const float*)d_in[3];   // [VOCAB, 64]
    const float* lin1  = (const float*)d_in[4];   // [3, 71, 64]
    const float* attl  = (const float*)d_in[5];   // [3, 64]
    const float* attr_ = (const float*)d_in[6];   // [3, 64]
    const float* lin2  = (const float*)d_in[7];   // [3, 64, 64]
    const float* gb    = (const float*)d_in[8];   // [3, 64]
    const float* fc1   = (const float*)d_in[9];   // [256, 20]
    const float* fb1   = (const float*)d_in[10];  // [20]
    const float* fc2   = (const float*)d_in[11];  // [20, 1]
    const float* fb2   = (const float*)d_in[12];  // [1]
    float* out = (float*)d_out;

    int nb = (NN + 7) / 8;  // edge kernel: warp per node

    k_csr<<<CSR_BLOCKS, CSR_THREADS>>>(ei, eattr);                   // 0
    k_gprep<<<NB_G, 256>>>(x, emb, lin1, attr_);                     // 1
    k_edge<<<nb, 256>>>(lin1, attl);                                 // 2
    k_upprep<<<NB_G, 256>>>(lin2, gb, lin1 + 1 * 71 * F, attr_ + 1 * F, 1);  // 3 <- PROFILED (clock canary)
    k_edge<<<nb, 256>>>(lin1 + 1 * 71 * F, attl + 1 * F);
    k_upprep<<<NB_G, 256>>>(lin2 + 1 * F * F, gb + 1 * F, lin1 + 2 * 71 * F, attr_ + 2 * F, 2);
    k_edge<<<nb, 256>>>(lin1 + 2 * 71 * F, attl + 2 * F);
    k_uphead<<<NB_G, 256>>>(lin2 + 2 * F * F, gb + 2 * F, fc1, fb1, fc2, fb2, out);
}